// round 14
// baseline (speedup 1.0000x reference)
#include <cuda_runtime.h>
#include <cuda_fp16.h>
#include <math.h>
#include <cstdint>
#include <cstddef>

// Problem constants
static constexpr int NN   = 32000;     // nodes
static constexpr int NB   = 16;        // graphs
static constexpr int NPG  = 2000;      // nodes per graph
static constexpr int KK   = 1600;      // clusters total
static constexpr int KPG  = 100;       // clusters per graph
static constexpr int DD   = 128;       // feature dim
static constexpr int EE   = 512000;    // edges
static constexpr int ADJ_ELEMS = KK * KK;
static constexpr int CAP  = 96;        // neighbor bucket capacity

// ---------------- scratch (__device__ globals) ------------------------------
__device__ uint32_t g_h16[(size_t)NN * DD / 2];      // packed fp16 input features
__device__ uint32_t g_x16[(size_t)NN * DD / 2];      // packed fp16 activations
__device__ uint32_t g_a16[(size_t)NN * KPG / 2];     // packed fp16 assign copy
__device__ uint32_t g_w1f[DD * DD / 2];              // weights, [N][K/2] fp16
__device__ uint32_t g_w2f[DD * DD / 2];
__device__ uint32_t g_w1p[(size_t)KK * DD / 2];
__device__ uint32_t g_w2p[(size_t)KK * KK / 2];
__device__ float g_feat[(size_t)NN * DD];
__device__ float g_assign[(size_t)NN * KPG];
__device__ float g_tmp[(size_t)NN * KPG];
__device__ int   g_degi[NN];
__device__ int   g_nbr[(size_t)NN * CAP];

// ---------------- helpers ----------------------------------------------------
__device__ __forceinline__ uint32_t smem_u32(const void* p) {
    uint32_t a;
    asm("{ .reg .u64 t; cvta.to.shared.u64 t, %1; cvt.u32.u64 %0, t; }" : "=r"(a) : "l"(p));
    return a;
}
__device__ __forceinline__ void cp16(uint32_t saddr, const void* g) {
    asm volatile("cp.async.ca.shared.global [%0], [%1], 16;" :: "r"(saddr), "l"(g) : "memory");
}
__device__ __forceinline__ void cp_commit() {
    asm volatile("cp.async.commit_group;" ::: "memory");
}
__device__ __forceinline__ void cp_wait0() {
    asm volatile("cp.async.wait_group 0;" ::: "memory");
}
__device__ __forceinline__ void ldm_x4(uint32_t* r, uint32_t saddr) {
    asm volatile("ldmatrix.sync.aligned.m8n8.x4.shared.b16 {%0,%1,%2,%3}, [%4];"
                 : "=r"(r[0]), "=r"(r[1]), "=r"(r[2]), "=r"(r[3]) : "r"(saddr));
}
__device__ __forceinline__ void mma_f16(float* c, const uint32_t* a,
                                        uint32_t b0, uint32_t b1) {
    asm volatile(
        "mma.sync.aligned.m16n8k16.row.col.f32.f16.f16.f32 "
        "{%0,%1,%2,%3}, {%4,%5,%6,%7}, {%8,%9}, {%0,%1,%2,%3};"
        : "+f"(c[0]), "+f"(c[1]), "+f"(c[2]), "+f"(c[3])
        : "r"(a[0]), "r"(a[1]), "r"(a[2]), "r"(a[3]), "r"(b0), "r"(b1));
}
__device__ __forceinline__ uint32_t cvt2h(float f0, float f1) {
    __half2 p = __halves2half2(__float2half_rn(f0), __float2half_rn(f1));
    return *reinterpret_cast<uint32_t*>(&p);
}
__device__ __forceinline__ void unpack2h(uint32_t w, float& f0, float& f1) {
    __half2 p = *reinterpret_cast<__half2*>(&w);
    f0 = __half2float(__low2half(p));
    f1 = __half2float(__high2half(p));
}

// ---------------- zero helpers ----------------------------------------------
__global__ void zero_f(float* __restrict__ p, size_t n) {
    size_t i = (size_t)blockIdx.x * blockDim.x + threadIdx.x;
    size_t st = (size_t)gridDim.x * blockDim.x;
    for (; i < n; i += st) p[i] = 0.f;
}
__global__ void zero_i(int* __restrict__ p, size_t n) {
    size_t i = (size_t)blockIdx.x * blockDim.x + threadIdx.x;
    size_t st = (size_t)gridDim.x * blockDim.x;
    for (; i < n; i += st) p[i] = 0;
}

// ---------------- bucket fill ------------------------------------------------
__global__ void fill_bucket_kernel(const int* __restrict__ src,
                                   const int* __restrict__ dst) {
    int e = blockIdx.x * blockDim.x + threadIdx.x;
    if (e >= EE) return;
    int d = dst[e];
    int p = atomicAdd(&g_degi[d], 1);
    if (p < CAP) g_nbr[(size_t)d * CAP + p] = src[e];
}

// ---------------- h -> packed fp16 ------------------------------------------
__global__ void cvt_h16_kernel(const float* __restrict__ h) {
    size_t i = (size_t)blockIdx.x * blockDim.x + threadIdx.x;
    if (i >= (size_t)NN * DD / 2) return;
    float2 v = ((const float2*)h)[i];
    g_h16[i] = cvt2h(v.x, v.y);
}

// ---------------- weight cvt+transpose --------------------------------------
__global__ void cvt_BT_kernel(const float* __restrict__ B,
                              uint32_t* __restrict__ Bp, int K2, int N) {
    int idx = blockIdx.x * blockDim.x + threadIdx.x;
    if (idx >= N * K2) return;
    int n = idx / K2, kp = idx - n * K2;
    Bp[idx] = cvt2h(B[(size_t)(2 * kp) * N + n], B[(size_t)(2 * kp + 1) * N + n]);
}

// ---------------- gather: x = h + mean nbr (fp16 neighbor stream) ------------
__global__ void gather_x_kernel(const float* __restrict__ h) {
    int n = (blockIdx.x * blockDim.x + threadIdx.x) >> 5;
    int lane = threadIdx.x & 31;
    if (n >= NN) return;
    int dg = min(g_degi[n], CAP);
    const int* nb = g_nbr + (size_t)n * CAP;
    float a0 = 0.f, a1 = 0.f, a2 = 0.f, a3 = 0.f;
    for (int j = 0; j < dg; j++) {
        const uint2 w = ((const uint2*)(g_h16 + (size_t)nb[j] * 64))[lane];
        float f0, f1, f2, f3;
        unpack2h(w.x, f0, f1);
        unpack2h(w.y, f2, f3);
        a0 += f0; a1 += f1; a2 += f2; a3 += f3;
    }
    float inv = 1.f / fmaxf((float)dg, 1.f);
    float4 hn = ((const float4*)(h + (size_t)n * DD))[lane];
    size_t base = (size_t)n * (DD / 2) + lane * 2;
    g_x16[base]     = cvt2h(hn.x + a0 * inv, hn.y + a1 * inv);
    g_x16[base + 1] = cvt2h(hn.z + a2 * inv, hn.w + a3 * inv);
}

// ================= FUSED pool1+pool2+softmax =================================
static constexpr int NCH = KK / 64;       // 25 chunks
static constexpr int S1  = 68;
static constexpr int S2  = 36;
static constexpr int XT_0    = 0;
static constexpr int W1_BASE = 128 * S1;               // 8704
static constexpr int W1_BUF  = 64 * S1;                // 4352
static constexpr int W2_BASE = W1_BASE + 2 * W1_BUF;   // 17408
static constexpr int W2_BUF  = 128 * S2;               // 4608
static constexpr int FUSED_W    = W2_BASE + 2 * W2_BUF;  // 26624 words
static constexpr int FUSED_SMEM = FUSED_W * 4;           // 106496 B

__global__ __launch_bounds__(256, 2)
void fused_pool_kernel(const float* __restrict__ b1p, const float* __restrict__ b2p) {
    extern __shared__ uint32_t sm[];
    const uint32_t sb = smem_u32(sm);
    const int mt128 = blockIdx.x;
    const int gz    = blockIdx.y;
    const int tid = threadIdx.x, wid = tid >> 5, lane = tid & 31;
    const int g = lane >> 2, tig = lane & 3;
    const int lrow = (lane < 16) ? lane : (lane - 16);
    const int lsel = (lane >= 16) ? 4 : 0;

    // ---- prologue: X tile + W1[0] + W2[0]
#pragma unroll
    for (int i = 0; i < 8; i++) {
        int q = tid + i * 256;
        int row = q >> 4, w = (q & 15) * 4;
        int grow = gz * NPG + min(mt128 * 128 + row, NPG - 1);
        cp16(sb + (uint32_t)(XT_0 + row * S1 + w) * 4, g_x16 + (size_t)grow * 64 + w);
    }
#pragma unroll
    for (int i = 0; i < 4; i++) {
        int q = tid + i * 256;
        int row = q >> 4, w = (q & 15) * 4;
        cp16(sb + (uint32_t)(W1_BASE + row * S1 + w) * 4, g_w1p + (size_t)row * 64 + w);
    }
#pragma unroll
    for (int i = 0; i < 4; i++) {
        int q = tid + i * 256;
        if (q < 800) {
            int row = q >> 3, w = (q & 7) * 4;
            cp16(sb + (uint32_t)(W2_BASE + row * S2 + w) * 4,
                 g_w2p + (size_t)(gz * 100 + row) * 800 + w);
        }
    }
    cp_commit();

    float c2[13][4];
#pragma unroll
    for (int nt = 0; nt < 13; nt++)
#pragma unroll
        for (int q = 0; q < 4; q++) c2[nt][q] = 0.f;

    for (int c = 0; c < NCH; c++) {
        cp_wait0();
        __syncthreads();

        if (c + 1 < NCH) {
            const int nb = (c + 1) & 1;
#pragma unroll
            for (int i = 0; i < 4; i++) {
                int q = tid + i * 256;
                int row = q >> 4, w = (q & 15) * 4;
                cp16(sb + (uint32_t)(W1_BASE + nb * W1_BUF + row * S1 + w) * 4,
                     g_w1p + (size_t)((c + 1) * 64 + row) * 64 + w);
            }
#pragma unroll
            for (int i = 0; i < 4; i++) {
                int q = tid + i * 256;
                if (q < 800) {
                    int row = q >> 3, w = (q & 7) * 4;
                    cp16(sb + (uint32_t)(W2_BASE + nb * W2_BUF + row * S2 + w) * 4,
                         g_w2p + (size_t)(gz * 100 + row) * 800 + (c + 1) * 32 + w);
                }
            }
            cp_commit();
        }

        // ---- stage1
        float c1[8][4];
#pragma unroll
        for (int nt = 0; nt < 8; nt++)
#pragma unroll
            for (int q = 0; q < 4; q++) c1[nt][q] = 0.f;

        const uint32_t w1b = (uint32_t)(W1_BASE + (c & 1) * W1_BUF);
        const uint32_t aRowOff = (uint32_t)((wid * 16 + lrow) * S1) * 4;
#pragma unroll
        for (int ks = 0; ks < 8; ks++) {
            const uint32_t ko = (uint32_t)(ks * 8 + lsel) * 4;
            uint32_t aa[4];
            ldm_x4(aa, sb + aRowOff + ko);
#pragma unroll
            for (int ng = 0; ng < 4; ng++) {
                uint32_t bb[4];
                const uint32_t ro = (uint32_t)((ng * 16 + lrow) * S1) * 4;
                ldm_x4(bb, sb + w1b * 4 + ro + ko);
#pragma unroll
                for (int sub = 0; sub < 2; sub++)
                    mma_f16(c1[ng * 2 + sub], aa, bb[sub], bb[2 + sub]);
            }
        }

        // ---- bias + relu
#pragma unroll
        for (int nt = 0; nt < 8; nt++) {
            const int colG = c * 64 + nt * 8 + 2 * tig;
            const float b0 = b1p[colG];
            const float b1 = b1p[colG + 1];
            c1[nt][0] = fmaxf(c1[nt][0] + b0, 0.f);
            c1[nt][1] = fmaxf(c1[nt][1] + b1, 0.f);
            c1[nt][2] = fmaxf(c1[nt][2] + b0, 0.f);
            c1[nt][3] = fmaxf(c1[nt][3] + b1, 0.f);
        }

        // ---- stage2
        const uint32_t w2b = (uint32_t)(W2_BASE + (c & 1) * W2_BUF);
#pragma unroll
        for (int ks = 0; ks < 4; ks++) {
            uint32_t a2[4];
            a2[0] = cvt2h(c1[2 * ks][0],     c1[2 * ks][1]);
            a2[1] = cvt2h(c1[2 * ks][2],     c1[2 * ks][3]);
            a2[2] = cvt2h(c1[2 * ks + 1][0], c1[2 * ks + 1][1]);
            a2[3] = cvt2h(c1[2 * ks + 1][2], c1[2 * ks + 1][3]);
            const uint32_t ko = (uint32_t)(ks * 8 + lsel) * 4;
#pragma unroll
            for (int ng = 0; ng < 7; ng++) {
                uint32_t bb[4];
                const uint32_t ro = (uint32_t)((ng * 16 + lrow) * S2) * 4;
                ldm_x4(bb, sb + w2b * 4 + ro + ko);
#pragma unroll
                for (int sub = 0; sub < 2; sub++) {
                    const int nt = ng * 2 + sub;
                    if (nt > 12) continue;
                    mma_f16(c2[nt], a2, bb[sub], bb[2 + sub]);
                }
            }
        }
    }

    // ---- fused epilogue: bias + relu + softmax, write assign (fp32 + fp16)
    const int rL0 = mt128 * 128 + wid * 16 + g;
    const int rL1 = rL0 + 8;
    float e[13][4];
    float mx0 = -1e30f, mx1 = -1e30f;
#pragma unroll
    for (int nt = 0; nt < 13; nt++) {
        const int col = nt * 8 + 2 * tig;
        if (col < KPG) {
            const float b0 = b2p[gz * KPG + col];
            const float b1 = b2p[gz * KPG + col + 1];
            e[nt][0] = fmaxf(c2[nt][0] + b0, 0.f);
            e[nt][1] = fmaxf(c2[nt][1] + b1, 0.f);
            e[nt][2] = fmaxf(c2[nt][2] + b0, 0.f);
            e[nt][3] = fmaxf(c2[nt][3] + b1, 0.f);
            mx0 = fmaxf(mx0, fmaxf(e[nt][0], e[nt][1]));
            mx1 = fmaxf(mx1, fmaxf(e[nt][2], e[nt][3]));
        } else {
            e[nt][0] = e[nt][1] = e[nt][2] = e[nt][3] = -1e30f;
        }
    }
    mx0 = fmaxf(mx0, __shfl_xor_sync(0xFFFFFFFFu, mx0, 1));
    mx0 = fmaxf(mx0, __shfl_xor_sync(0xFFFFFFFFu, mx0, 2));
    mx1 = fmaxf(mx1, __shfl_xor_sync(0xFFFFFFFFu, mx1, 1));
    mx1 = fmaxf(mx1, __shfl_xor_sync(0xFFFFFFFFu, mx1, 2));
    float s0 = 0.f, s1 = 0.f;
#pragma unroll
    for (int nt = 0; nt < 13; nt++) {
        e[nt][0] = expf(e[nt][0] - mx0);
        e[nt][1] = expf(e[nt][1] - mx0);
        e[nt][2] = expf(e[nt][2] - mx1);
        e[nt][3] = expf(e[nt][3] - mx1);
        const int col = nt * 8 + 2 * tig;
        if (col < KPG) { s0 += e[nt][0] + e[nt][1]; s1 += e[nt][2] + e[nt][3]; }
    }
    s0 += __shfl_xor_sync(0xFFFFFFFFu, s0, 1);
    s0 += __shfl_xor_sync(0xFFFFFFFFu, s0, 2);
    s1 += __shfl_xor_sync(0xFFFFFFFFu, s1, 1);
    s1 += __shfl_xor_sync(0xFFFFFFFFu, s1, 2);
    const float inv0 = 1.f / (s0 + 1e-13f);
    const float inv1 = 1.f / (s1 + 1e-13f);
#pragma unroll
    for (int nt = 0; nt < 13; nt++) {
        const int col = nt * 8 + 2 * tig;
        if (col >= KPG) continue;
        const float v0 = e[nt][0] * inv0, v1 = e[nt][1] * inv0;
        const float v2 = e[nt][2] * inv1, v3 = e[nt][3] * inv1;
        if (rL0 < NPG) {
            *(float2*)(g_assign + (size_t)(gz * NPG + rL0) * KPG + col) = make_float2(v0, v1);
            g_a16[(size_t)(gz * NPG + rL0) * 50 + (col >> 1)] = cvt2h(v0, v1);
        }
        if (rL1 < NPG) {
            *(float2*)(g_assign + (size_t)(gz * NPG + rL1) * KPG + col) = make_float2(v2, v3);
            g_a16[(size_t)(gz * NPG + rL1) * 50 + (col >> 1)] = cvt2h(v2, v3);
        }
    }
}

// ================= FUSED feat branch =========================================
static constexpr int FS  = 68;
static constexpr int FX  = 0;
static constexpr int FW1 = 128 * FS;
static constexpr int FW2 = 2 * 128 * FS;
static constexpr int FEAT_SMEM = 3 * 128 * FS * 4;

__global__ __launch_bounds__(256, 2)
void feat_fused_kernel(const float* __restrict__ b1f, const float* __restrict__ b2f) {
    extern __shared__ uint32_t smf[];
    const uint32_t sb = smem_u32(smf);
    const int bm = blockIdx.x * 128;
    const int tid = threadIdx.x, wid = tid >> 5, lane = tid & 31;
    const int g = lane >> 2, tig = lane & 3;
    const int lrow = (lane < 16) ? lane : (lane - 16);
    const int lsel = (lane >= 16) ? 4 : 0;

#pragma unroll
    for (int i = 0; i < 8; i++) {
        int q = tid + i * 256;
        int row = q >> 4, w = (q & 15) * 4;
        cp16(sb + (uint32_t)(FX + row * FS + w) * 4,  g_x16 + (size_t)(bm + row) * 64 + w);
        cp16(sb + (uint32_t)(FW1 + row * FS + w) * 4, g_w1f + (size_t)row * 64 + w);
        cp16(sb + (uint32_t)(FW2 + row * FS + w) * 4, g_w2f + (size_t)row * 64 + w);
    }
    cp_commit();
    cp_wait0();
    __syncthreads();

    float c1[16][4];
#pragma unroll
    for (int nt = 0; nt < 16; nt++)
#pragma unroll
        for (int q = 0; q < 4; q++) c1[nt][q] = 0.f;

    const uint32_t aRowOff = (uint32_t)((wid * 16 + lrow) * FS) * 4;
#pragma unroll
    for (int ks = 0; ks < 8; ks++) {
        const uint32_t ko = (uint32_t)(ks * 8 + lsel) * 4;
        uint32_t aa[4];
        ldm_x4(aa, sb + aRowOff + ko);
#pragma unroll
        for (int ng = 0; ng < 8; ng++) {
            uint32_t bb[4];
            ldm_x4(bb, sb + (uint32_t)(FW1 * 4) + (uint32_t)((ng * 16 + lrow) * FS) * 4 + ko);
#pragma unroll
            for (int sub = 0; sub < 2; sub++)
                mma_f16(c1[ng * 2 + sub], aa, bb[sub], bb[2 + sub]);
        }
    }
#pragma unroll
    for (int nt = 0; nt < 16; nt++) {
        const int col = nt * 8 + 2 * tig;
        const float b0 = b1f[col];
        const float b1 = b1f[col + 1];
        c1[nt][0] = fmaxf(c1[nt][0] + b0, 0.f);
        c1[nt][1] = fmaxf(c1[nt][1] + b1, 0.f);
        c1[nt][2] = fmaxf(c1[nt][2] + b0, 0.f);
        c1[nt][3] = fmaxf(c1[nt][3] + b1, 0.f);
    }
    uint32_t a2[8][4];
#pragma unroll
    for (int ks = 0; ks < 8; ks++) {
        a2[ks][0] = cvt2h(c1[2 * ks][0],     c1[2 * ks][1]);
        a2[ks][1] = cvt2h(c1[2 * ks][2],     c1[2 * ks][3]);
        a2[ks][2] = cvt2h(c1[2 * ks + 1][0], c1[2 * ks + 1][1]);
        a2[ks][3] = cvt2h(c1[2 * ks + 1][2], c1[2 * ks + 1][3]);
    }

    float c2[16][4];
#pragma unroll
    for (int nt = 0; nt < 16; nt++)
#pragma unroll
        for (int q = 0; q < 4; q++) c2[nt][q] = 0.f;
#pragma unroll
    for (int ks = 0; ks < 8; ks++) {
        const uint32_t ko = (uint32_t)(ks * 8 + lsel) * 4;
#pragma unroll
        for (int ng = 0; ng < 8; ng++) {
            uint32_t bb[4];
            ldm_x4(bb, sb + (uint32_t)(FW2 * 4) + (uint32_t)((ng * 16 + lrow) * FS) * 4 + ko);
#pragma unroll
            for (int sub = 0; sub < 2; sub++)
                mma_f16(c2[ng * 2 + sub], a2[ks], bb[sub], bb[2 + sub]);
        }
    }

    const int r0 = bm + wid * 16 + g;
    const int r1 = r0 + 8;
#pragma unroll
    for (int nt = 0; nt < 16; nt++) {
        const int col = nt * 8 + 2 * tig;
        const float b0 = b2f[col];
        const float b1 = b2f[col + 1];
        *(float2*)(g_feat + (size_t)r0 * DD + col) =
            make_float2(fmaxf(c2[nt][0] + b0, 0.f), fmaxf(c2[nt][1] + b1, 0.f));
        *(float2*)(g_feat + (size_t)r1 * DD + col) =
            make_float2(fmaxf(c2[nt][2] + b0, 0.f), fmaxf(c2[nt][3] + b1, 0.f));
    }
}

// ---------------- gather: tmp[n] = sum nbr assign (fp16 stream) --------------
__global__ void gather_tmp_kernel() {
    int n = (blockIdx.x * blockDim.x + threadIdx.x) >> 5;
    int lane = threadIdx.x & 31;
    if (n >= NN) return;
    int dg = min(g_degi[n], CAP);
    const int* nb = g_nbr + (size_t)n * CAP;
    float a0 = 0.f, a1 = 0.f, a2 = 0.f, a3 = 0.f;
    const bool hi = (lane < 18);
    for (int j = 0; j < dg; j++) {
        const uint32_t* ar = g_a16 + (size_t)nb[j] * 50;
        float f0, f1;
        unpack2h(ar[lane], f0, f1);
        a0 += f0; a1 += f1;
        if (hi) {
            unpack2h(ar[lane + 32], f0, f1);
            a2 += f0; a3 += f1;
        }
    }
    float* tp = g_tmp + (size_t)n * KPG;
    *(float2*)(tp + 2 * lane) = make_float2(a0, a1);
    if (hi) *(float2*)(tp + 64 + 2 * lane) = make_float2(a2, a3);
}

// ---------------- merged hpool + adj ----------------------------------------
__global__ __launch_bounds__(256)
void hpool_adj_kernel(float* __restrict__ out) {
    const int g = blockIdx.y;
    const int split = blockIdx.x;
    const int kbeg = split * (NPG / 8);
    const int kend = kbeg + (NPG / 8);
    const float* A = g_assign + (size_t)g * NPG * KPG;
    const float* T = g_tmp + (size_t)g * NPG * KPG;
    const float* F = g_feat + (size_t)g * NPG * DD;
    float* outAdj = out;
    float* outHp  = out + ADJ_ELEMS;

    __shared__ float As[8][KPG];
    __shared__ float Ts[8][KPG];
    __shared__ float Fs[8][DD];
    const int tx = threadIdx.x & 15;
    const int ty = threadIdx.x >> 4;

    float accH[7][8];
    float accA[7][7];
#pragma unroll
    for (int i = 0; i < 7; i++) {
#pragma unroll
        for (int j = 0; j < 8; j++) accH[i][j] = 0.f;
#pragma unroll
        for (int j = 0; j < 7; j++) accA[i][j] = 0.f;
    }

    for (int k0 = kbeg; k0 < kend; k0 += 8) {
        int kc = min(8, kend - k0);
        for (int idx = threadIdx.x; idx < 8 * KPG; idx += 256) {
            int r = idx / KPG, c = idx % KPG;
            As[r][c] = (r < kc) ? A[(size_t)(k0 + r) * KPG + c] : 0.f;
            Ts[r][c] = (r < kc) ? T[(size_t)(k0 + r) * KPG + c] : 0.f;
        }
        for (int idx = threadIdx.x; idx < 8 * DD; idx += 256) {
            int r = idx >> 7, c = idx & 127;
            Fs[r][c] = (r < kc) ? F[(size_t)(k0 + r) * DD + c] : 0.f;
        }
        __syncthreads();
#pragma unroll
        for (int k = 0; k < 8; k++) {
            float a[7], f[8], b[7];
#pragma unroll
            for (int i = 0; i < 7; i++) {
                int c = ty + 16 * i;
                a[i] = (c < KPG) ? As[k][c] : 0.f;
            }
#pragma unroll
            for (int j = 0; j < 8; j++) f[j] = Fs[k][tx + 16 * j];
#pragma unroll
            for (int j = 0; j < 7; j++) {
                int c = tx + 16 * j;
                b[j] = (c < KPG) ? Ts[k][c] : 0.f;
            }
#pragma unroll
            for (int i = 0; i < 7; i++) {
#pragma unroll
                for (int j = 0; j < 8; j++) accH[i][j] += a[i] * f[j];
#pragma unroll
                for (int j = 0; j < 7; j++) accA[i][j] += a[i] * b[j];
            }
        }
        __syncthreads();
    }
#pragma unroll
    for (int i = 0; i < 7; i++) {
        int c1 = ty + 16 * i;
        if (c1 >= KPG) continue;
#pragma unroll
        for (int j = 0; j < 8; j++) {
            int d = tx + 16 * j;
            atomicAdd(&outHp[(size_t)(g * KPG + c1) * DD + d], accH[i][j]);
        }
#pragma unroll
        for (int j = 0; j < 7; j++) {
            int c2 = tx + 16 * j;
            if (c2 >= KPG) continue;
            atomicAdd(&outAdj[(size_t)(g * KPG + c1) * KK + (g * KPG + c2)], accA[i][j]);
        }
    }
}

// ---------------- launch ----------------------------------------------------
extern "C" void kernel_launch(void* const* d_in, const int* in_sizes, int n_in,
                              void* d_out, int out_size) {
    const float* h   = (const float*)d_in[0];
    const int*   src = (const int*)d_in[1];
    const int*   dst = (const int*)d_in[2];
    const float* W1f = (const float*)d_in[3];
    const float* b1f = (const float*)d_in[4];
    const float* W2f = (const float*)d_in[5];
    const float* b2f = (const float*)d_in[6];
    const float* W1p = (const float*)d_in[7];
    const float* b1p = (const float*)d_in[8];
    const float* W2p = (const float*)d_in[9];
    const float* b2p = (const float*)d_in[10];
    float* out = (float*)d_out;

    uint32_t *w1f, *w2f, *w1p, *w2p;
    int* degi;
    cudaGetSymbolAddress((void**)&w1f,  g_w1f);
    cudaGetSymbolAddress((void**)&w2f,  g_w2f);
    cudaGetSymbolAddress((void**)&w1p,  g_w1p);
    cudaGetSymbolAddress((void**)&w2p,  g_w2p);
    cudaGetSymbolAddress((void**)&degi, g_degi);

    cudaFuncSetAttribute(fused_pool_kernel, cudaFuncAttributeMaxDynamicSharedMemorySize, FUSED_SMEM);
    cudaFuncSetAttribute(feat_fused_kernel, cudaFuncAttributeMaxDynamicSharedMemorySize, FEAT_SMEM);

    // prep
    zero_i<<<128, 256>>>(degi, (size_t)NN);
    fill_bucket_kernel<<<(EE + 255) / 256, 256>>>(src, dst);
    cvt_h16_kernel<<<((size_t)NN * DD / 2 + 255) / 256, 256>>>(h);
    gather_x_kernel<<<(NN * 32 + 255) / 256, 256>>>(h);
    cvt_BT_kernel<<<((size_t)KK * DD / 2 + 255) / 256, 256>>>(W1p, w1p, DD / 2, KK);
    cvt_BT_kernel<<<((size_t)KK * KK / 2 + 255) / 256, 256>>>(W2p, w2p, KK / 2, KK);

    // fused pool1+pool2+softmax -> assign (fp32 + fp16 copy)
    fused_pool_kernel<<<dim3(16, NB), 256, FUSED_SMEM>>>(b1p, b2p);

    // feat branch (both layers fused)
    zero_f<<<1024, 256>>>(out, (size_t)out_size);
    cvt_BT_kernel<<<(DD * DD / 2 + 255) / 256, 256>>>(W1f, w1f, DD / 2, DD);
    cvt_BT_kernel<<<(DD * DD / 2 + 255) / 256, 256>>>(W2f, w2f, DD / 2, DD);
    feat_fused_kernel<<<250, 256, FEAT_SMEM>>>(b1f, b2f);

    // tmp gather (fp16 stream), merged output GEMMs
    gather_tmp_kernel<<<(NN * 32 + 255) / 256, 256>>>();
    hpool_adj_kernel<<<dim3(8, NB), 256>>>(out);
}

// round 15
// speedup vs baseline: 1.0451x; 1.0451x over previous
#include <cuda_runtime.h>
#include <cuda_fp16.h>
#include <math.h>
#include <cstdint>
#include <cstddef>

// Problem constants
static constexpr int NN   = 32000;     // nodes
static constexpr int NB   = 16;        // graphs
static constexpr int NPG  = 2000;      // nodes per graph
static constexpr int KK   = 1600;      // clusters total
static constexpr int KPG  = 100;       // clusters per graph
static constexpr int DD   = 128;       // feature dim
static constexpr int EE   = 512000;    // edges
static constexpr int ADJ_ELEMS = KK * KK;
static constexpr int CAP  = 96;        // neighbor bucket capacity

// ---------------- scratch (__device__ globals) ------------------------------
__device__ uint32_t g_x16[(size_t)NN * DD / 2];      // packed fp16 activations
__device__ uint32_t g_w1f[DD * DD / 2];              // weights, [N][K/2] fp16
__device__ uint32_t g_w2f[DD * DD / 2];
__device__ uint32_t g_w1p[(size_t)KK * DD / 2];
__device__ uint32_t g_w2p[(size_t)KK * KK / 2];
__device__ float g_feat[(size_t)NN * DD];
__device__ float g_assign[(size_t)NN * KPG];
__device__ float g_tmp[(size_t)NN * KPG];
__device__ int   g_degi[NN];
__device__ int   g_nbr[(size_t)NN * CAP];

// ---------------- helpers ----------------------------------------------------
__device__ __forceinline__ uint32_t smem_u32(const void* p) {
    uint32_t a;
    asm("{ .reg .u64 t; cvta.to.shared.u64 t, %1; cvt.u32.u64 %0, t; }" : "=r"(a) : "l"(p));
    return a;
}
__device__ __forceinline__ void cp16(uint32_t saddr, const void* g) {
    asm volatile("cp.async.ca.shared.global [%0], [%1], 16;" :: "r"(saddr), "l"(g) : "memory");
}
__device__ __forceinline__ void cp_commit() {
    asm volatile("cp.async.commit_group;" ::: "memory");
}
__device__ __forceinline__ void cp_wait0() {
    asm volatile("cp.async.wait_group 0;" ::: "memory");
}
__device__ __forceinline__ void ldm_x4(uint32_t* r, uint32_t saddr) {
    asm volatile("ldmatrix.sync.aligned.m8n8.x4.shared.b16 {%0,%1,%2,%3}, [%4];"
                 : "=r"(r[0]), "=r"(r[1]), "=r"(r[2]), "=r"(r[3]) : "r"(saddr));
}
__device__ __forceinline__ void mma_f16(float* c, const uint32_t* a,
                                        uint32_t b0, uint32_t b1) {
    asm volatile(
        "mma.sync.aligned.m16n8k16.row.col.f32.f16.f16.f32 "
        "{%0,%1,%2,%3}, {%4,%5,%6,%7}, {%8,%9}, {%0,%1,%2,%3};"
        : "+f"(c[0]), "+f"(c[1]), "+f"(c[2]), "+f"(c[3])
        : "r"(a[0]), "r"(a[1]), "r"(a[2]), "r"(a[3]), "r"(b0), "r"(b1));
}
__device__ __forceinline__ uint32_t cvt2h(float f0, float f1) {
    __half2 p = __halves2half2(__float2half_rn(f0), __float2half_rn(f1));
    return *reinterpret_cast<uint32_t*>(&p);
}

// ---------------- zero helpers ----------------------------------------------
__global__ void zero_f(float* __restrict__ p, size_t n) {
    size_t i = (size_t)blockIdx.x * blockDim.x + threadIdx.x;
    size_t st = (size_t)gridDim.x * blockDim.x;
    for (; i < n; i += st) p[i] = 0.f;
}
__global__ void zero_i(int* __restrict__ p, size_t n) {
    size_t i = (size_t)blockIdx.x * blockDim.x + threadIdx.x;
    size_t st = (size_t)gridDim.x * blockDim.x;
    for (; i < n; i += st) p[i] = 0;
}

// ---------------- bucket fill ------------------------------------------------
__global__ void fill_bucket_kernel(const int* __restrict__ src,
                                   const int* __restrict__ dst) {
    int e = blockIdx.x * blockDim.x + threadIdx.x;
    if (e >= EE) return;
    int d = dst[e];
    int p = atomicAdd(&g_degi[d], 1);
    if (p < CAP) g_nbr[(size_t)d * CAP + p] = src[e];
}

// ---------------- ALL weight cvt+transpose in one kernel ---------------------
// segments: [w1f: 8192][w2f: 8192][w1p: 102400][w2p: 1280000] words
__global__ void cvt_all_kernel(const float* __restrict__ W1f, const float* __restrict__ W2f,
                               const float* __restrict__ W1p, const float* __restrict__ W2p) {
    int idx = blockIdx.x * blockDim.x + threadIdx.x;
    const int n1 = DD * DD / 2;                 // 8192
    const int n2 = n1 + DD * DD / 2;            // 16384
    const int n3 = n2 + KK * DD / 2;            // 118784
    const int n4 = n3 + KK * (KK / 2);          // 1398784
    if (idx >= n4) return;
    const float* B;
    uint32_t* out;
    int K2, N, local;
    if (idx < n1)      { B = W1f; out = g_w1f; K2 = DD / 2; N = DD; local = idx; }
    else if (idx < n2) { B = W2f; out = g_w2f; K2 = DD / 2; N = DD; local = idx - n1; }
    else if (idx < n3) { B = W1p; out = g_w1p; K2 = DD / 2; N = KK; local = idx - n2; }
    else               { B = W2p; out = g_w2p; K2 = KK / 2; N = KK; local = idx - n3; }
    int n = local / K2, kp = local - n * K2;
    out[local] = cvt2h(B[(size_t)(2 * kp) * N + n], B[(size_t)(2 * kp + 1) * N + n]);
}

// ---------------- gather: x = h + mean nbr (shfl-broadcast indices) ----------
__global__ void gather_x_kernel(const float* __restrict__ h) {
    int n = (blockIdx.x * blockDim.x + threadIdx.x) >> 5;
    int lane = threadIdx.x & 31;
    if (n >= NN) return;
    int dg = min(g_degi[n], CAP);
    const int* nb = g_nbr + (size_t)n * CAP;
    int myIdx0 = (lane < dg) ? nb[lane] : 0;
    int myIdx1 = (32 + lane < dg) ? nb[32 + lane] : 0;
    int myIdx2 = (64 + lane < dg) ? nb[64 + lane] : 0;
    float a0 = 0.f, a1 = 0.f, a2 = 0.f, a3 = 0.f;
    for (int j = 0; j < dg; j++) {
        int s = (j < 32) ? __shfl_sync(0xFFFFFFFFu, myIdx0, j)
              : (j < 64) ? __shfl_sync(0xFFFFFFFFu, myIdx1, j - 32)
                         : __shfl_sync(0xFFFFFFFFu, myIdx2, j - 64);
        float4 v = ((const float4*)(h + (size_t)s * DD))[lane];
        a0 += v.x; a1 += v.y; a2 += v.z; a3 += v.w;
    }
    float inv = 1.f / fmaxf((float)dg, 1.f);
    float4 hn = ((const float4*)(h + (size_t)n * DD))[lane];
    size_t base = (size_t)n * (DD / 2) + lane * 2;
    g_x16[base]     = cvt2h(hn.x + a0 * inv, hn.y + a1 * inv);
    g_x16[base + 1] = cvt2h(hn.z + a2 * inv, hn.w + a3 * inv);
}

// ================= FUSED pool1+pool2+softmax =================================
static constexpr int NCH = KK / 64;       // 25 chunks
static constexpr int S1  = 68;
static constexpr int S2  = 36;
static constexpr int XT_0    = 0;
static constexpr int W1_BASE = 128 * S1;               // 8704
static constexpr int W1_BUF  = 64 * S1;                // 4352
static constexpr int W2_BASE = W1_BASE + 2 * W1_BUF;   // 17408
static constexpr int W2_BUF  = 128 * S2;               // 4608
static constexpr int FUSED_W    = W2_BASE + 2 * W2_BUF;  // 26624 words
static constexpr int FUSED_SMEM = FUSED_W * 4;           // 106496 B

__global__ __launch_bounds__(256, 2)
void fused_pool_kernel(const float* __restrict__ b1p, const float* __restrict__ b2p) {
    extern __shared__ uint32_t sm[];
    const uint32_t sb = smem_u32(sm);
    const int mt128 = blockIdx.x;
    const int gz    = blockIdx.y;
    const int tid = threadIdx.x, wid = tid >> 5, lane = tid & 31;
    const int g = lane >> 2, tig = lane & 3;
    const int lrow = (lane < 16) ? lane : (lane - 16);
    const int lsel = (lane >= 16) ? 4 : 0;

    // ---- prologue: X tile + W1[0] + W2[0]
#pragma unroll
    for (int i = 0; i < 8; i++) {
        int q = tid + i * 256;
        int row = q >> 4, w = (q & 15) * 4;
        int grow = gz * NPG + min(mt128 * 128 + row, NPG - 1);
        cp16(sb + (uint32_t)(XT_0 + row * S1 + w) * 4, g_x16 + (size_t)grow * 64 + w);
    }
#pragma unroll
    for (int i = 0; i < 4; i++) {
        int q = tid + i * 256;
        int row = q >> 4, w = (q & 15) * 4;
        cp16(sb + (uint32_t)(W1_BASE + row * S1 + w) * 4, g_w1p + (size_t)row * 64 + w);
    }
#pragma unroll
    for (int i = 0; i < 4; i++) {
        int q = tid + i * 256;
        if (q < 800) {
            int row = q >> 3, w = (q & 7) * 4;
            cp16(sb + (uint32_t)(W2_BASE + row * S2 + w) * 4,
                 g_w2p + (size_t)(gz * 100 + row) * 800 + w);
        }
    }
    cp_commit();

    float c2[13][4];
#pragma unroll
    for (int nt = 0; nt < 13; nt++)
#pragma unroll
        for (int q = 0; q < 4; q++) c2[nt][q] = 0.f;

    for (int c = 0; c < NCH; c++) {
        cp_wait0();
        __syncthreads();

        if (c + 1 < NCH) {
            const int nb = (c + 1) & 1;
#pragma unroll
            for (int i = 0; i < 4; i++) {
                int q = tid + i * 256;
                int row = q >> 4, w = (q & 15) * 4;
                cp16(sb + (uint32_t)(W1_BASE + nb * W1_BUF + row * S1 + w) * 4,
                     g_w1p + (size_t)((c + 1) * 64 + row) * 64 + w);
            }
#pragma unroll
            for (int i = 0; i < 4; i++) {
                int q = tid + i * 256;
                if (q < 800) {
                    int row = q >> 3, w = (q & 7) * 4;
                    cp16(sb + (uint32_t)(W2_BASE + nb * W2_BUF + row * S2 + w) * 4,
                         g_w2p + (size_t)(gz * 100 + row) * 800 + (c + 1) * 32 + w);
                }
            }
            cp_commit();
        }

        // ---- stage1
        float c1[8][4];
#pragma unroll
        for (int nt = 0; nt < 8; nt++)
#pragma unroll
            for (int q = 0; q < 4; q++) c1[nt][q] = 0.f;

        const uint32_t w1b = (uint32_t)(W1_BASE + (c & 1) * W1_BUF);
        const uint32_t aRowOff = (uint32_t)((wid * 16 + lrow) * S1) * 4;
#pragma unroll
        for (int ks = 0; ks < 8; ks++) {
            const uint32_t ko = (uint32_t)(ks * 8 + lsel) * 4;
            uint32_t aa[4];
            ldm_x4(aa, sb + aRowOff + ko);
#pragma unroll
            for (int ng = 0; ng < 4; ng++) {
                uint32_t bb[4];
                const uint32_t ro = (uint32_t)((ng * 16 + lrow) * S1) * 4;
                ldm_x4(bb, sb + w1b * 4 + ro + ko);
#pragma unroll
                for (int sub = 0; sub < 2; sub++)
                    mma_f16(c1[ng * 2 + sub], aa, bb[sub], bb[2 + sub]);
            }
        }

        // ---- bias + relu
#pragma unroll
        for (int nt = 0; nt < 8; nt++) {
            const int colG = c * 64 + nt * 8 + 2 * tig;
            const float b0 = b1p[colG];
            const float b1 = b1p[colG + 1];
            c1[nt][0] = fmaxf(c1[nt][0] + b0, 0.f);
            c1[nt][1] = fmaxf(c1[nt][1] + b1, 0.f);
            c1[nt][2] = fmaxf(c1[nt][2] + b0, 0.f);
            c1[nt][3] = fmaxf(c1[nt][3] + b1, 0.f);
        }

        // ---- stage2
        const uint32_t w2b = (uint32_t)(W2_BASE + (c & 1) * W2_BUF);
#pragma unroll
        for (int ks = 0; ks < 4; ks++) {
            uint32_t a2[4];
            a2[0] = cvt2h(c1[2 * ks][0],     c1[2 * ks][1]);
            a2[1] = cvt2h(c1[2 * ks][2],     c1[2 * ks][3]);
            a2[2] = cvt2h(c1[2 * ks + 1][0], c1[2 * ks + 1][1]);
            a2[3] = cvt2h(c1[2 * ks + 1][2], c1[2 * ks + 1][3]);
            const uint32_t ko = (uint32_t)(ks * 8 + lsel) * 4;
#pragma unroll
            for (int ng = 0; ng < 7; ng++) {
                uint32_t bb[4];
                const uint32_t ro = (uint32_t)((ng * 16 + lrow) * S2) * 4;
                ldm_x4(bb, sb + w2b * 4 + ro + ko);
#pragma unroll
                for (int sub = 0; sub < 2; sub++) {
                    const int nt = ng * 2 + sub;
                    if (nt > 12) continue;
                    mma_f16(c2[nt], a2, bb[sub], bb[2 + sub]);
                }
            }
        }
    }

    // ---- fused epilogue: bias + relu + softmax, write assign
    const int rL0 = mt128 * 128 + wid * 16 + g;
    const int rL1 = rL0 + 8;
    float e[13][4];
    float mx0 = -1e30f, mx1 = -1e30f;
#pragma unroll
    for (int nt = 0; nt < 13; nt++) {
        const int col = nt * 8 + 2 * tig;
        if (col < KPG) {
            const float b0 = b2p[gz * KPG + col];
            const float b1 = b2p[gz * KPG + col + 1];
            e[nt][0] = fmaxf(c2[nt][0] + b0, 0.f);
            e[nt][1] = fmaxf(c2[nt][1] + b1, 0.f);
            e[nt][2] = fmaxf(c2[nt][2] + b0, 0.f);
            e[nt][3] = fmaxf(c2[nt][3] + b1, 0.f);
            mx0 = fmaxf(mx0, fmaxf(e[nt][0], e[nt][1]));
            mx1 = fmaxf(mx1, fmaxf(e[nt][2], e[nt][3]));
        } else {
            e[nt][0] = e[nt][1] = e[nt][2] = e[nt][3] = -1e30f;
        }
    }
    mx0 = fmaxf(mx0, __shfl_xor_sync(0xFFFFFFFFu, mx0, 1));
    mx0 = fmaxf(mx0, __shfl_xor_sync(0xFFFFFFFFu, mx0, 2));
    mx1 = fmaxf(mx1, __shfl_xor_sync(0xFFFFFFFFu, mx1, 1));
    mx1 = fmaxf(mx1, __shfl_xor_sync(0xFFFFFFFFu, mx1, 2));
    float s0 = 0.f, s1 = 0.f;
#pragma unroll
    for (int nt = 0; nt < 13; nt++) {
        e[nt][0] = expf(e[nt][0] - mx0);
        e[nt][1] = expf(e[nt][1] - mx0);
        e[nt][2] = expf(e[nt][2] - mx1);
        e[nt][3] = expf(e[nt][3] - mx1);
        const int col = nt * 8 + 2 * tig;
        if (col < KPG) { s0 += e[nt][0] + e[nt][1]; s1 += e[nt][2] + e[nt][3]; }
    }
    s0 += __shfl_xor_sync(0xFFFFFFFFu, s0, 1);
    s0 += __shfl_xor_sync(0xFFFFFFFFu, s0, 2);
    s1 += __shfl_xor_sync(0xFFFFFFFFu, s1, 1);
    s1 += __shfl_xor_sync(0xFFFFFFFFu, s1, 2);
    const float inv0 = 1.f / (s0 + 1e-13f);
    const float inv1 = 1.f / (s1 + 1e-13f);
#pragma unroll
    for (int nt = 0; nt < 13; nt++) {
        const int col = nt * 8 + 2 * tig;
        if (col >= KPG) continue;
        if (rL0 < NPG)
            *(float2*)(g_assign + (size_t)(gz * NPG + rL0) * KPG + col) =
                make_float2(e[nt][0] * inv0, e[nt][1] * inv0);
        if (rL1 < NPG)
            *(float2*)(g_assign + (size_t)(gz * NPG + rL1) * KPG + col) =
                make_float2(e[nt][2] * inv1, e[nt][3] * inv1);
    }
}

// ================= FUSED feat branch =========================================
static constexpr int FS  = 68;
static constexpr int FX  = 0;
static constexpr int FW1 = 128 * FS;
static constexpr int FW2 = 2 * 128 * FS;
static constexpr int FEAT_SMEM = 3 * 128 * FS * 4;

__global__ __launch_bounds__(256, 2)
void feat_fused_kernel(const float* __restrict__ b1f, const float* __restrict__ b2f) {
    extern __shared__ uint32_t smf[];
    const uint32_t sb = smem_u32(smf);
    const int bm = blockIdx.x * 128;
    const int tid = threadIdx.x, wid = tid >> 5, lane = tid & 31;
    const int g = lane >> 2, tig = lane & 3;
    const int lrow = (lane < 16) ? lane : (lane - 16);
    const int lsel = (lane >= 16) ? 4 : 0;

#pragma unroll
    for (int i = 0; i < 8; i++) {
        int q = tid + i * 256;
        int row = q >> 4, w = (q & 15) * 4;
        cp16(sb + (uint32_t)(FX + row * FS + w) * 4,  g_x16 + (size_t)(bm + row) * 64 + w);
        cp16(sb + (uint32_t)(FW1 + row * FS + w) * 4, g_w1f + (size_t)row * 64 + w);
        cp16(sb + (uint32_t)(FW2 + row * FS + w) * 4, g_w2f + (size_t)row * 64 + w);
    }
    cp_commit();
    cp_wait0();
    __syncthreads();

    float c1[16][4];
#pragma unroll
    for (int nt = 0; nt < 16; nt++)
#pragma unroll
        for (int q = 0; q < 4; q++) c1[nt][q] = 0.f;

    const uint32_t aRowOff = (uint32_t)((wid * 16 + lrow) * FS) * 4;
#pragma unroll
    for (int ks = 0; ks < 8; ks++) {
        const uint32_t ko = (uint32_t)(ks * 8 + lsel) * 4;
        uint32_t aa[4];
        ldm_x4(aa, sb + aRowOff + ko);
#pragma unroll
        for (int ng = 0; ng < 8; ng++) {
            uint32_t bb[4];
            ldm_x4(bb, sb + (uint32_t)(FW1 * 4) + (uint32_t)((ng * 16 + lrow) * FS) * 4 + ko);
#pragma unroll
            for (int sub = 0; sub < 2; sub++)
                mma_f16(c1[ng * 2 + sub], aa, bb[sub], bb[2 + sub]);
        }
    }
#pragma unroll
    for (int nt = 0; nt < 16; nt++) {
        const int col = nt * 8 + 2 * tig;
        const float b0 = b1f[col];
        const float b1 = b1f[col + 1];
        c1[nt][0] = fmaxf(c1[nt][0] + b0, 0.f);
        c1[nt][1] = fmaxf(c1[nt][1] + b1, 0.f);
        c1[nt][2] = fmaxf(c1[nt][2] + b0, 0.f);
        c1[nt][3] = fmaxf(c1[nt][3] + b1, 0.f);
    }
    uint32_t a2[8][4];
#pragma unroll
    for (int ks = 0; ks < 8; ks++) {
        a2[ks][0] = cvt2h(c1[2 * ks][0],     c1[2 * ks][1]);
        a2[ks][1] = cvt2h(c1[2 * ks][2],     c1[2 * ks][3]);
        a2[ks][2] = cvt2h(c1[2 * ks + 1][0], c1[2 * ks + 1][1]);
        a2[ks][3] = cvt2h(c1[2 * ks + 1][2], c1[2 * ks + 1][3]);
    }

    float c2[16][4];
#pragma unroll
    for (int nt = 0; nt < 16; nt++)
#pragma unroll
        for (int q = 0; q < 4; q++) c2[nt][q] = 0.f;
#pragma unroll
    for (int ks = 0; ks < 8; ks++) {
        const uint32_t ko = (uint32_t)(ks * 8 + lsel) * 4;
#pragma unroll
        for (int ng = 0; ng < 8; ng++) {
            uint32_t bb[4];
            ldm_x4(bb, sb + (uint32_t)(FW2 * 4) + (uint32_t)((ng * 16 + lrow) * FS) * 4 + ko);
#pragma unroll
            for (int sub = 0; sub < 2; sub++)
                mma_f16(c2[ng * 2 + sub], a2[ks], bb[sub], bb[2 + sub]);
        }
    }

    const int r0 = bm + wid * 16 + g;
    const int r1 = r0 + 8;
#pragma unroll
    for (int nt = 0; nt < 16; nt++) {
        const int col = nt * 8 + 2 * tig;
        const float b0 = b2f[col];
        const float b1 = b2f[col + 1];
        *(float2*)(g_feat + (size_t)r0 * DD + col) =
            make_float2(fmaxf(c2[nt][0] + b0, 0.f), fmaxf(c2[nt][1] + b1, 0.f));
        *(float2*)(g_feat + (size_t)r1 * DD + col) =
            make_float2(fmaxf(c2[nt][2] + b0, 0.f), fmaxf(c2[nt][3] + b1, 0.f));
    }
}

// ---------------- gather: tmp[n] = sum nbr assign (shfl-broadcast) -----------
__global__ void gather_tmp_kernel() {
    int n = (blockIdx.x * blockDim.x + threadIdx.x) >> 5;
    int lane = threadIdx.x & 31;
    if (n >= NN) return;
    int dg = min(g_degi[n], CAP);
    const int* nb = g_nbr + (size_t)n * CAP;
    int myIdx0 = (lane < dg) ? nb[lane] : 0;
    int myIdx1 = (32 + lane < dg) ? nb[32 + lane] : 0;
    int myIdx2 = (64 + lane < dg) ? nb[64 + lane] : 0;
    float a0 = 0.f, a1 = 0.f, a2 = 0.f, a3 = 0.f;
    for (int j = 0; j < dg; j++) {
        int s = (j < 32) ? __shfl_sync(0xFFFFFFFFu, myIdx0, j)
              : (j < 64) ? __shfl_sync(0xFFFFFFFFu, myIdx1, j - 32)
                         : __shfl_sync(0xFFFFFFFFu, myIdx2, j - 64);
        const float* ar = g_assign + (size_t)s * KPG;
        a0 += ar[lane];
        a1 += ar[lane + 32];
        a2 += ar[lane + 64];
        if (lane < 4) a3 += ar[lane + 96];
    }
    float* tp = g_tmp + (size_t)n * KPG;
    tp[lane]      = a0;
    tp[lane + 32] = a1;
    tp[lane + 64] = a2;
    if (lane < 4) tp[lane + 96] = a3;
}

// ---------------- merged hpool + adj (16 splits) -----------------------------
static constexpr int NSPLIT = 16;
__global__ __launch_bounds__(256)
void hpool_adj_kernel(float* __restrict__ out) {
    const int g = blockIdx.y;
    const int split = blockIdx.x;
    const int kbeg = split * (NPG / NSPLIT);
    const int kend = kbeg + (NPG / NSPLIT);
    const float* A = g_assign + (size_t)g * NPG * KPG;
    const float* T = g_tmp + (size_t)g * NPG * KPG;
    const float* F = g_feat + (size_t)g * NPG * DD;
    float* outAdj = out;
    float* outHp  = out + ADJ_ELEMS;

    __shared__ float As[8][KPG];
    __shared__ float Ts[8][KPG];
    __shared__ float Fs[8][DD];
    const int tx = threadIdx.x & 15;
    const int ty = threadIdx.x >> 4;

    float accH[7][8];
    float accA[7][7];
#pragma unroll
    for (int i = 0; i < 7; i++) {
#pragma unroll
        for (int j = 0; j < 8; j++) accH[i][j] = 0.f;
#pragma unroll
        for (int j = 0; j < 7; j++) accA[i][j] = 0.f;
    }

    for (int k0 = kbeg; k0 < kend; k0 += 8) {
        int kc = min(8, kend - k0);
        for (int idx = threadIdx.x; idx < 8 * KPG; idx += 256) {
            int r = idx / KPG, c = idx % KPG;
            As[r][c] = (r < kc) ? A[(size_t)(k0 + r) * KPG + c] : 0.f;
            Ts[r][c] = (r < kc) ? T[(size_t)(k0 + r) * KPG + c] : 0.f;
        }
        for (int idx = threadIdx.x; idx < 8 * DD; idx += 256) {
            int r = idx >> 7, c = idx & 127;
            Fs[r][c] = (r < kc) ? F[(size_t)(k0 + r) * DD + c] : 0.f;
        }
        __syncthreads();
#pragma unroll
        for (int k = 0; k < 8; k++) {
            float a[7], f[8], b[7];
#pragma unroll
            for (int i = 0; i < 7; i++) {
                int c = ty + 16 * i;
                a[i] = (c < KPG) ? As[k][c] : 0.f;
            }
#pragma unroll
            for (int j = 0; j < 8; j++) f[j] = Fs[k][tx + 16 * j];
#pragma unroll
            for (int j = 0; j < 7; j++) {
                int c = tx + 16 * j;
                b[j] = (c < KPG) ? Ts[k][c] : 0.f;
            }
#pragma unroll
            for (int i = 0; i < 7; i++) {
#pragma unroll
                for (int j = 0; j < 8; j++) accH[i][j] += a[i] * f[j];
#pragma unroll
                for (int j = 0; j < 7; j++) accA[i][j] += a[i] * b[j];
            }
        }
        __syncthreads();
    }
#pragma unroll
    for (int i = 0; i < 7; i++) {
        int c1 = ty + 16 * i;
        if (c1 >= KPG) continue;
#pragma unroll
        for (int j = 0; j < 8; j++) {
            int d = tx + 16 * j;
            atomicAdd(&outHp[(size_t)(g * KPG + c1) * DD + d], accH[i][j]);
        }
#pragma unroll
        for (int j = 0; j < 7; j++) {
            int c2 = tx + 16 * j;
            if (c2 >= KPG) continue;
            atomicAdd(&outAdj[(size_t)(g * KPG + c1) * KK + (g * KPG + c2)], accA[i][j]);
        }
    }
}

// ---------------- launch ----------------------------------------------------
extern "C" void kernel_launch(void* const* d_in, const int* in_sizes, int n_in,
                              void* d_out, int out_size) {
    const float* h   = (const float*)d_in[0];
    const int*   src = (const int*)d_in[1];
    const int*   dst = (const int*)d_in[2];
    const float* W1f = (const float*)d_in[3];
    const float* b1f = (const float*)d_in[4];
    const float* W2f = (const float*)d_in[5];
    const float* b2f = (const float*)d_in[6];
    const float* W1p = (const float*)d_in[7];
    const float* b1p = (const float*)d_in[8];
    const float* W2p = (const float*)d_in[9];
    const float* b2p = (const float*)d_in[10];
    float* out = (float*)d_out;

    int* degi;
    cudaGetSymbolAddress((void**)&degi, g_degi);

    cudaFuncSetAttribute(fused_pool_kernel, cudaFuncAttributeMaxDynamicSharedMemorySize, FUSED_SMEM);
    cudaFuncSetAttribute(feat_fused_kernel, cudaFuncAttributeMaxDynamicSharedMemorySize, FEAT_SMEM);

    // prep
    zero_i<<<128, 256>>>(degi, (size_t)NN);
    fill_bucket_kernel<<<(EE + 255) / 256, 256>>>(src, dst);
    gather_x_kernel<<<(NN * 32 + 255) / 256, 256>>>(h);
    cvt_all_kernel<<<(1398784 + 255) / 256, 256>>>(W1f, W2f, W1p, W2p);

    // fused pool1+pool2+softmax -> assign
    fused_pool_kernel<<<dim3(16, NB), 256, FUSED_SMEM>>>(b1p, b2p);

    // feat branch (both layers fused)
    zero_f<<<1024, 256>>>(out, (size_t)out_size);
    feat_fused_kernel<<<250, 256, FEAT_SMEM>>>(b1f, b2f);

    // tmp gather, merged output GEMMs
    gather_tmp_kernel<<<(NN * 32 + 255) / 256, 256>>>();
    hpool_adj_kernel<<<dim3(NSPLIT, NB), 256>>>(out);
}

// round 17
// speedup vs baseline: 1.0741x; 1.0278x over previous
#include <cuda_runtime.h>
#include <cuda_fp16.h>
#include <math.h>
#include <cstdint>
#include <cstddef>

// Problem constants
static constexpr int NN   = 32000;     // nodes
static constexpr int NB   = 16;        // graphs
static constexpr int NPG  = 2000;      // nodes per graph
static constexpr int KK   = 1600;      // clusters total
static constexpr int KPG  = 100;       // clusters per graph
static constexpr int DD   = 128;       // feature dim
static constexpr int EE   = 512000;    // edges
static constexpr int ADJ_ELEMS = KK * KK;
static constexpr int CAP  = 96;        // neighbor bucket capacity

// ---------------- scratch (__device__ globals) ------------------------------
__device__ uint32_t g_x16[(size_t)NN * DD / 2];      // packed fp16 activations
__device__ uint32_t g_w1f[DD * DD / 2];              // weights, [N][K/2] fp16
__device__ uint32_t g_w2f[DD * DD / 2];
__device__ uint32_t g_w1p[(size_t)KK * DD / 2];
__device__ uint32_t g_w2p[(size_t)KK * KK / 2];
__device__ float g_feat[(size_t)NN * DD];
__device__ float g_assign[(size_t)NN * KPG];
__device__ float g_tmp[(size_t)NN * KPG];
__device__ int   g_degi[NN];
__device__ int   g_nbr[(size_t)NN * CAP];

// ---------------- helpers ----------------------------------------------------
__device__ __forceinline__ uint32_t smem_u32(const void* p) {
    uint32_t a;
    asm("{ .reg .u64 t; cvta.to.shared.u64 t, %1; cvt.u32.u64 %0, t; }" : "=r"(a) : "l"(p));
    return a;
}
__device__ __forceinline__ void cp16(uint32_t saddr, const void* g) {
    asm volatile("cp.async.ca.shared.global [%0], [%1], 16;" :: "r"(saddr), "l"(g) : "memory");
}
__device__ __forceinline__ void cp_commit() {
    asm volatile("cp.async.commit_group;" ::: "memory");
}
__device__ __forceinline__ void cp_wait0() {
    asm volatile("cp.async.wait_group 0;" ::: "memory");
}
__device__ __forceinline__ void ldm_x4(uint32_t* r, uint32_t saddr) {
    asm volatile("ldmatrix.sync.aligned.m8n8.x4.shared.b16 {%0,%1,%2,%3}, [%4];"
                 : "=r"(r[0]), "=r"(r[1]), "=r"(r[2]), "=r"(r[3]) : "r"(saddr));
}
__device__ __forceinline__ void mma_f16(float* c, const uint32_t* a,
                                        uint32_t b0, uint32_t b1) {
    asm volatile(
        "mma.sync.aligned.m16n8k16.row.col.f32.f16.f16.f32 "
        "{%0,%1,%2,%3}, {%4,%5,%6,%7}, {%8,%9}, {%0,%1,%2,%3};"
        : "+f"(c[0]), "+f"(c[1]), "+f"(c[2]), "+f"(c[3])
        : "r"(a[0]), "r"(a[1]), "r"(a[2]), "r"(a[3]), "r"(b0), "r"(b1));
}
__device__ __forceinline__ uint32_t cvt2h(float f0, float f1) {
    __half2 p = __halves2half2(__float2half_rn(f0), __float2half_rn(f1));
    return *reinterpret_cast<uint32_t*>(&p);
}

// ---------------- zero helpers ----------------------------------------------
__global__ void zero_f(float* __restrict__ p, size_t n) {
    size_t i = (size_t)blockIdx.x * blockDim.x + threadIdx.x;
    size_t st = (size_t)gridDim.x * blockDim.x;
    for (; i < n; i += st) p[i] = 0.f;
}
__global__ void zero_i(int* __restrict__ p, size_t n) {
    size_t i = (size_t)blockIdx.x * blockDim.x + threadIdx.x;
    size_t st = (size_t)gridDim.x * blockDim.x;
    for (; i < n; i += st) p[i] = 0;
}

// ---------------- bucket fill ------------------------------------------------
__global__ void fill_bucket_kernel(const int* __restrict__ src,
                                   const int* __restrict__ dst) {
    int e = blockIdx.x * blockDim.x + threadIdx.x;
    if (e >= EE) return;
    int d = dst[e];
    int p = atomicAdd(&g_degi[d], 1);
    if (p < CAP) g_nbr[(size_t)d * CAP + p] = src[e];
}

// ---------------- tiled coalesced weight cvt+transpose ------------------------
// Per tile: 32 n-cols x 32 kp-rows (= 64 fp32 k-rows). Reads coalesced rows of
// W [K][N]; writes coalesced packed words of Wt [N][K/2].
// blocks: [0,8) w1f, [8,16) w2f, [16,116) w1p, [116,1366) w2p.
__global__ __launch_bounds__(256)
void cvt_tiled_kernel(const float* __restrict__ W1f, const float* __restrict__ W2f,
                      const float* __restrict__ W1p, const float* __restrict__ W2p) {
    __shared__ float s[64][33];
    const int b = blockIdx.x;
    const float* B;
    uint32_t* out;
    int K2, N, local;
    if (b < 8)        { B = W1f; out = g_w1f; K2 = 64;  N = 128;  local = b; }
    else if (b < 16)  { B = W2f; out = g_w2f; K2 = 64;  N = 128;  local = b - 8; }
    else if (b < 116) { B = W1p; out = g_w1p; K2 = 64;  N = 1600; local = b - 16; }
    else              { B = W2p; out = g_w2p; K2 = 800; N = 1600; local = b - 116; }
    const int tilesN = N >> 5;
    const int tn = local % tilesN, tk = local / tilesN;
    const int n0 = tn * 32, kp0 = tk * 32;
    const int tx = threadIdx.x & 31, ty = threadIdx.x >> 5;

#pragma unroll
    for (int r = 0; r < 8; r++) {
        int k = kp0 * 2 + ty + r * 8;          // 64 consecutive k rows
        s[ty + r * 8][tx] = B[(size_t)k * N + n0 + tx];
    }
    __syncthreads();
#pragma unroll
    for (int q = 0; q < 4; q++) {
        int n = n0 + ty + q * 8;
        int kp = kp0 + tx;
        out[(size_t)n * K2 + kp] = cvt2h(s[2 * tx][ty + q * 8], s[2 * tx + 1][ty + q * 8]);
    }
}

// ---------------- gather: x = h + mean nbr (shfl idx, unrolled loads) --------
__global__ void gather_x_kernel(const float* __restrict__ h) {
    int n = (blockIdx.x * blockDim.x + threadIdx.x) >> 5;
    int lane = threadIdx.x & 31;
    if (n >= NN) return;
    int dg = min(g_degi[n], CAP);
    const int* nb = g_nbr + (size_t)n * CAP;
    int myIdx0 = (lane < dg) ? nb[lane] : 0;
    int myIdx1 = (32 + lane < dg) ? nb[32 + lane] : 0;
    int myIdx2 = (64 + lane < dg) ? nb[64 + lane] : 0;
    float a0 = 0.f, a1 = 0.f, a2 = 0.f, a3 = 0.f;
#pragma unroll 4
    for (int j = 0; j < dg; j++) {
        int s = (j < 32) ? __shfl_sync(0xFFFFFFFFu, myIdx0, j)
              : (j < 64) ? __shfl_sync(0xFFFFFFFFu, myIdx1, j - 32)
                         : __shfl_sync(0xFFFFFFFFu, myIdx2, j - 64);
        float4 v = ((const float4*)(h + (size_t)s * DD))[lane];
        a0 += v.x; a1 += v.y; a2 += v.z; a3 += v.w;
    }
    float inv = 1.f / fmaxf((float)dg, 1.f);
    float4 hn = ((const float4*)(h + (size_t)n * DD))[lane];
    size_t base = (size_t)n * (DD / 2) + lane * 2;
    g_x16[base]     = cvt2h(hn.x + a0 * inv, hn.y + a1 * inv);
    g_x16[base + 1] = cvt2h(hn.z + a2 * inv, hn.w + a3 * inv);
}

// ================= FUSED pool1+pool2+softmax =================================
static constexpr int NCH = KK / 64;       // 25 chunks
static constexpr int S1  = 68;
static constexpr int S2  = 36;
static constexpr int XT_0    = 0;
static constexpr int W1_BASE = 128 * S1;               // 8704
static constexpr int W1_BUF  = 64 * S1;                // 4352
static constexpr int W2_BASE = W1_BASE + 2 * W1_BUF;   // 17408
static constexpr int W2_BUF  = 128 * S2;               // 4608
static constexpr int FUSED_W    = W2_BASE + 2 * W2_BUF;  // 26624 words
static constexpr int FUSED_SMEM = FUSED_W * 4;           // 106496 B

__global__ __launch_bounds__(256, 2)
void fused_pool_kernel(const float* __restrict__ b1p, const float* __restrict__ b2p) {
    extern __shared__ uint32_t sm[];
    const uint32_t sb = smem_u32(sm);
    const int mt128 = blockIdx.x;
    const int gz    = blockIdx.y;
    const int tid = threadIdx.x, wid = tid >> 5, lane = tid & 31;
    const int g = lane >> 2, tig = lane & 3;
    const int lrow = (lane < 16) ? lane : (lane - 16);
    const int lsel = (lane >= 16) ? 4 : 0;

    // ---- prologue: X tile + W1[0] + W2[0]
#pragma unroll
    for (int i = 0; i < 8; i++) {
        int q = tid + i * 256;
        int row = q >> 4, w = (q & 15) * 4;
        int grow = gz * NPG + min(mt128 * 128 + row, NPG - 1);
        cp16(sb + (uint32_t)(XT_0 + row * S1 + w) * 4, g_x16 + (size_t)grow * 64 + w);
    }
#pragma unroll
    for (int i = 0; i < 4; i++) {
        int q = tid + i * 256;
        int row = q >> 4, w = (q & 15) * 4;
        cp16(sb + (uint32_t)(W1_BASE + row * S1 + w) * 4, g_w1p + (size_t)row * 64 + w);
    }
#pragma unroll
    for (int i = 0; i < 4; i++) {
        int q = tid + i * 256;
        if (q < 800) {
            int row = q >> 3, w = (q & 7) * 4;
            cp16(sb + (uint32_t)(W2_BASE + row * S2 + w) * 4,
                 g_w2p + (size_t)(gz * 100 + row) * 800 + w);
        }
    }
    cp_commit();

    float c2[13][4];
#pragma unroll
    for (int nt = 0; nt < 13; nt++)
#pragma unroll
        for (int q = 0; q < 4; q++) c2[nt][q] = 0.f;

    for (int c = 0; c < NCH; c++) {
        cp_wait0();
        __syncthreads();

        if (c + 1 < NCH) {
            const int nb = (c + 1) & 1;
#pragma unroll
            for (int i = 0; i < 4; i++) {
                int q = tid + i * 256;
                int row = q >> 4, w = (q & 15) * 4;
                cp16(sb + (uint32_t)(W1_BASE + nb * W1_BUF + row * S1 + w) * 4,
                     g_w1p + (size_t)((c + 1) * 64 + row) * 64 + w);
            }
#pragma unroll
            for (int i = 0; i < 4; i++) {
                int q = tid + i * 256;
                if (q < 800) {
                    int row = q >> 3, w = (q & 7) * 4;
                    cp16(sb + (uint32_t)(W2_BASE + nb * W2_BUF + row * S2 + w) * 4,
                         g_w2p + (size_t)(gz * 100 + row) * 800 + (c + 1) * 32 + w);
                }
            }
            cp_commit();
        }

        // ---- stage1
        float c1[8][4];
#pragma unroll
        for (int nt = 0; nt < 8; nt++)
#pragma unroll
            for (int q = 0; q < 4; q++) c1[nt][q] = 0.f;

        const uint32_t w1b = (uint32_t)(W1_BASE + (c & 1) * W1_BUF);
        const uint32_t aRowOff = (uint32_t)((wid * 16 + lrow) * S1) * 4;
#pragma unroll
        for (int ks = 0; ks < 8; ks++) {
            const uint32_t ko = (uint32_t)(ks * 8 + lsel) * 4;
            uint32_t aa[4];
            ldm_x4(aa, sb + aRowOff + ko);
#pragma unroll
            for (int ng = 0; ng < 4; ng++) {
                uint32_t bb[4];
                const uint32_t ro = (uint32_t)((ng * 16 + lrow) * S1) * 4;
                ldm_x4(bb, sb + w1b * 4 + ro + ko);
#pragma unroll
                for (int sub = 0; sub < 2; sub++)
                    mma_f16(c1[ng * 2 + sub], aa, bb[sub], bb[2 + sub]);
            }
        }

        // ---- bias + relu
#pragma unroll
        for (int nt = 0; nt < 8; nt++) {
            const int colG = c * 64 + nt * 8 + 2 * tig;
            const float b0 = b1p[colG];
            const float b1 = b1p[colG + 1];
            c1[nt][0] = fmaxf(c1[nt][0] + b0, 0.f);
            c1[nt][1] = fmaxf(c1[nt][1] + b1, 0.f);
            c1[nt][2] = fmaxf(c1[nt][2] + b0, 0.f);
            c1[nt][3] = fmaxf(c1[nt][3] + b1, 0.f);
        }

        // ---- stage2
        const uint32_t w2b = (uint32_t)(W2_BASE + (c & 1) * W2_BUF);
#pragma unroll
        for (int ks = 0; ks < 4; ks++) {
            uint32_t a2[4];
            a2[0] = cvt2h(c1[2 * ks][0],     c1[2 * ks][1]);
            a2[1] = cvt2h(c1[2 * ks][2],     c1[2 * ks][3]);
            a2[2] = cvt2h(c1[2 * ks + 1][0], c1[2 * ks + 1][1]);
            a2[3] = cvt2h(c1[2 * ks + 1][2], c1[2 * ks + 1][3]);
            const uint32_t ko = (uint32_t)(ks * 8 + lsel) * 4;
#pragma unroll
            for (int ng = 0; ng < 7; ng++) {
                uint32_t bb[4];
                const uint32_t ro = (uint32_t)((ng * 16 + lrow) * S2) * 4;
                ldm_x4(bb, sb + w2b * 4 + ro + ko);
#pragma unroll
                for (int sub = 0; sub < 2; sub++) {
                    const int nt = ng * 2 + sub;
                    if (nt > 12) continue;
                    mma_f16(c2[nt], a2, bb[sub], bb[2 + sub]);
                }
            }
        }
    }

    // ---- fused epilogue: bias + relu + softmax, write assign
    const int rL0 = mt128 * 128 + wid * 16 + g;
    const int rL1 = rL0 + 8;
    float e[13][4];
    float mx0 = -1e30f, mx1 = -1e30f;
#pragma unroll
    for (int nt = 0; nt < 13; nt++) {
        const int col = nt * 8 + 2 * tig;
        if (col < KPG) {
            const float b0 = b2p[gz * KPG + col];
            const float b1 = b2p[gz * KPG + col + 1];
            e[nt][0] = fmaxf(c2[nt][0] + b0, 0.f);
            e[nt][1] = fmaxf(c2[nt][1] + b1, 0.f);
            e[nt][2] = fmaxf(c2[nt][2] + b0, 0.f);
            e[nt][3] = fmaxf(c2[nt][3] + b1, 0.f);
            mx0 = fmaxf(mx0, fmaxf(e[nt][0], e[nt][1]));
            mx1 = fmaxf(mx1, fmaxf(e[nt][2], e[nt][3]));
        } else {
            e[nt][0] = e[nt][1] = e[nt][2] = e[nt][3] = -1e30f;
        }
    }
    mx0 = fmaxf(mx0, __shfl_xor_sync(0xFFFFFFFFu, mx0, 1));
    mx0 = fmaxf(mx0, __shfl_xor_sync(0xFFFFFFFFu, mx0, 2));
    mx1 = fmaxf(mx1, __shfl_xor_sync(0xFFFFFFFFu, mx1, 1));
    mx1 = fmaxf(mx1, __shfl_xor_sync(0xFFFFFFFFu, mx1, 2));
    float s0 = 0.f, s1 = 0.f;
#pragma unroll
    for (int nt = 0; nt < 13; nt++) {
        e[nt][0] = expf(e[nt][0] - mx0);
        e[nt][1] = expf(e[nt][1] - mx0);
        e[nt][2] = expf(e[nt][2] - mx1);
        e[nt][3] = expf(e[nt][3] - mx1);
        const int col = nt * 8 + 2 * tig;
        if (col < KPG) { s0 += e[nt][0] + e[nt][1]; s1 += e[nt][2] + e[nt][3]; }
    }
    s0 += __shfl_xor_sync(0xFFFFFFFFu, s0, 1);
    s0 += __shfl_xor_sync(0xFFFFFFFFu, s0, 2);
    s1 += __shfl_xor_sync(0xFFFFFFFFu, s1, 1);
    s1 += __shfl_xor_sync(0xFFFFFFFFu, s1, 2);
    const float inv0 = 1.f / (s0 + 1e-13f);
    const float inv1 = 1.f / (s1 + 1e-13f);
#pragma unroll
    for (int nt = 0; nt < 13; nt++) {
        const int col = nt * 8 + 2 * tig;
        if (col >= KPG) continue;
        if (rL0 < NPG)
            *(float2*)(g_assign + (size_t)(gz * NPG + rL0) * KPG + col) =
                make_float2(e[nt][0] * inv0, e[nt][1] * inv0);
        if (rL1 < NPG)
            *(float2*)(g_assign + (size_t)(gz * NPG + rL1) * KPG + col) =
                make_float2(e[nt][2] * inv1, e[nt][3] * inv1);
    }
}

// ================= FUSED feat branch =========================================
static constexpr int FS  = 68;
static constexpr int FX  = 0;
static constexpr int FW1 = 128 * FS;
static constexpr int FW2 = 2 * 128 * FS;
static constexpr int FEAT_SMEM = 3 * 128 * FS * 4;

__global__ __launch_bounds__(256, 2)
void feat_fused_kernel(const float* __restrict__ b1f, const float* __restrict__ b2f) {
    extern __shared__ uint32_t smf[];
    const uint32_t sb = smem_u32(smf);
    const int bm = blockIdx.x * 128;
    const int tid = threadIdx.x, wid = tid >> 5, lane = tid & 31;
    const int g = lane >> 2, tig = lane & 3;
    const int lrow = (lane < 16) ? lane : (lane - 16);
    const int lsel = (lane >= 16) ? 4 : 0;

#pragma unroll
    for (int i = 0; i < 8; i++) {
        int q = tid + i * 256;
        int row = q >> 4, w = (q & 15) * 4;
        cp16(sb + (uint32_t)(FX + row * FS + w) * 4,  g_x16 + (size_t)(bm + row) * 64 + w);
        cp16(sb + (uint32_t)(FW1 + row * FS + w) * 4, g_w1f + (size_t)row * 64 + w);
        cp16(sb + (uint32_t)(FW2 + row * FS + w) * 4, g_w2f + (size_t)row * 64 + w);
    }
    cp_commit();
    cp_wait0();
    __syncthreads();

    float c1[16][4];
#pragma unroll
    for (int nt = 0; nt < 16; nt++)
#pragma unroll
        for (int q = 0; q < 4; q++) c1[nt][q] = 0.f;

    const uint32_t aRowOff = (uint32_t)((wid * 16 + lrow) * FS) * 4;
#pragma unroll
    for (int ks = 0; ks < 8; ks++) {
        const uint32_t ko = (uint32_t)(ks * 8 + lsel) * 4;
        uint32_t aa[4];
        ldm_x4(aa, sb + aRowOff + ko);
#pragma unroll
        for (int ng = 0; ng < 8; ng++) {
            uint32_t bb[4];
            ldm_x4(bb, sb + (uint32_t)(FW1 * 4) + (uint32_t)((ng * 16 + lrow) * FS) * 4 + ko);
#pragma unroll
            for (int sub = 0; sub < 2; sub++)
                mma_f16(c1[ng * 2 + sub], aa, bb[sub], bb[2 + sub]);
        }
    }
#pragma unroll
    for (int nt = 0; nt < 16; nt++) {
        const int col = nt * 8 + 2 * tig;
        const float b0 = b1f[col];
        const float b1 = b1f[col + 1];
        c1[nt][0] = fmaxf(c1[nt][0] + b0, 0.f);
        c1[nt][1] = fmaxf(c1[nt][1] + b1, 0.f);
        c1[nt][2] = fmaxf(c1[nt][2] + b0, 0.f);
        c1[nt][3] = fmaxf(c1[nt][3] + b1, 0.f);
    }
    uint32_t a2[8][4];
#pragma unroll
    for (int ks = 0; ks < 8; ks++) {
        a2[ks][0] = cvt2h(c1[2 * ks][0],     c1[2 * ks][1]);
        a2[ks][1] = cvt2h(c1[2 * ks][2],     c1[2 * ks][3]);
        a2[ks][2] = cvt2h(c1[2 * ks + 1][0], c1[2 * ks + 1][1]);
        a2[ks][3] = cvt2h(c1[2 * ks + 1][2], c1[2 * ks + 1][3]);
    }

    float c2[16][4];
#pragma unroll
    for (int nt = 0; nt < 16; nt++)
#pragma unroll
        for (int q = 0; q < 4; q++) c2[nt][q] = 0.f;
#pragma unroll
    for (int ks = 0; ks < 8; ks++) {
        const uint32_t ko = (uint32_t)(ks * 8 + lsel) * 4;
#pragma unroll
        for (int ng = 0; ng < 8; ng++) {
            uint32_t bb[4];
            ldm_x4(bb, sb + (uint32_t)(FW2 * 4) + (uint32_t)((ng * 16 + lrow) * FS) * 4 + ko);
#pragma unroll
            for (int sub = 0; sub < 2; sub++)
                mma_f16(c2[ng * 2 + sub], a2[ks], bb[sub], bb[2 + sub]);
        }
    }

    const int r0 = bm + wid * 16 + g;
    const int r1 = r0 + 8;
#pragma unroll
    for (int nt = 0; nt < 16; nt++) {
        const int col = nt * 8 + 2 * tig;
        const float b0 = b2f[col];
        const float b1 = b2f[col + 1];
        *(float2*)(g_feat + (size_t)r0 * DD + col) =
            make_float2(fmaxf(c2[nt][0] + b0, 0.f), fmaxf(c2[nt][1] + b1, 0.f));
        *(float2*)(g_feat + (size_t)r1 * DD + col) =
            make_float2(fmaxf(c2[nt][2] + b0, 0.f), fmaxf(c2[nt][3] + b1, 0.f));
    }
}

// ---------------- gather: tmp[n] = sum nbr assign (shfl idx, unrolled) -------
__global__ void gather_tmp_kernel() {
    int n = (blockIdx.x * blockDim.x + threadIdx.x) >> 5;
    int lane = threadIdx.x & 31;
    if (n >= NN) return;
    int dg = min(g_degi[n], CAP);
    const int* nb = g_nbr + (size_t)n * CAP;
    int myIdx0 = (lane < dg) ? nb[lane] : 0;
    int myIdx1 = (32 + lane < dg) ? nb[32 + lane] : 0;
    int myIdx2 = (64 + lane < dg) ? nb[64 + lane] : 0;
    float a0 = 0.f, a1 = 0.f, a2 = 0.f, a3 = 0.f;
#pragma unroll 4
    for (int j = 0; j < dg; j++) {
        int s = (j < 32) ? __shfl_sync(0xFFFFFFFFu, myIdx0, j)
              : (j < 64) ? __shfl_sync(0xFFFFFFFFu, myIdx1, j - 32)
                         : __shfl_sync(0xFFFFFFFFu, myIdx2, j - 64);
        const float* ar = g_assign + (size_t)s * KPG;
        a0 += ar[lane];
        a1 += ar[lane + 32];
        a2 += ar[lane + 64];
        if (lane < 4) a3 += ar[lane + 96];
    }
    float* tp = g_tmp + (size_t)n * KPG;
    tp[lane]      = a0;
    tp[lane + 32] = a1;
    tp[lane + 64] = a2;
    if (lane < 4) tp[lane + 96] = a3;
}

// ---------------- merged hpool + adj (16 splits) -----------------------------
static constexpr int NSPLIT = 16;
__global__ __launch_bounds__(256)
void hpool_adj_kernel(float* __restrict__ out) {
    const int g = blockIdx.y;
    const int split = blockIdx.x;
    const int kbeg = split * (NPG / NSPLIT);
    const int kend = kbeg + (NPG / NSPLIT);
    const float* A = g_assign + (size_t)g * NPG * KPG;
    const float* T = g_tmp + (size_t)g * NPG * KPG;
    const float* F = g_feat + (size_t)g * NPG * DD;
    float* outAdj = out;
    float* outHp  = out + ADJ_ELEMS;

    __shared__ float As[8][KPG];
    __shared__ float Ts[8][KPG];
    __shared__ float Fs[8][DD];
    const int tx = threadIdx.x & 15;
    const int ty = threadIdx.x >> 4;

    float accH[7][8];
    float accA[7][7];
#pragma unroll
    for (int i = 0; i < 7; i++) {
#pragma unroll
        for (int j = 0; j < 8; j++) accH[i][j] = 0.f;
#pragma unroll
        for (int j = 0; j < 7; j++) accA[i][j] = 0.f;
    }

    for (int k0 = kbeg; k0 < kend; k0 += 8) {
        int kc = min(8, kend - k0);
        for (int idx = threadIdx.x; idx < 8 * KPG; idx += 256) {
            int r = idx / KPG, c = idx % KPG;
            As[r][c] = (r < kc) ? A[(size_t)(k0 + r) * KPG + c] : 0.f;
            Ts[r][c] = (r < kc) ? T[(size_t)(k0 + r) * KPG + c] : 0.f;
        }
        for (int idx = threadIdx.x; idx < 8 * DD; idx += 256) {
            int r = idx >> 7, c = idx & 127;
            Fs[r][c] = (r < kc) ? F[(size_t)(k0 + r) * DD + c] : 0.f;
        }
        __syncthreads();
#pragma unroll
        for (int k = 0; k < 8; k++) {
            float a[7], f[8], b[7];
#pragma unroll
            for (int i = 0; i < 7; i++) {
                int c = ty + 16 * i;
                a[i] = (c < KPG) ? As[k][c] : 0.f;
            }
#pragma unroll
            for (int j = 0; j < 8; j++) f[j] = Fs[k][tx + 16 * j];
#pragma unroll
            for (int j = 0; j < 7; j++) {
                int c = tx + 16 * j;
                b[j] = (c < KPG) ? Ts[k][c] : 0.f;
            }
#pragma unroll
            for (int i = 0; i < 7; i++) {
#pragma unroll
                for (int j = 0; j < 8; j++) accH[i][j] += a[i] * f[j];
#pragma unroll
                for (int j = 0; j < 7; j++) accA[i][j] += a[i] * b[j];
            }
        }
        __syncthreads();
    }
#pragma unroll
    for (int i = 0; i < 7; i++) {
        int c1 = ty + 16 * i;
        if (c1 >= KPG) continue;
#pragma unroll
        for (int j = 0; j < 8; j++) {
            int d = tx + 16 * j;
            atomicAdd(&outHp[(size_t)(g * KPG + c1) * DD + d], accH[i][j]);
        }
#pragma unroll
        for (int j = 0; j < 7; j++) {
            int c2 = tx + 16 * j;
            if (c2 >= KPG) continue;
            atomicAdd(&outAdj[(size_t)(g * KPG + c1) * KK + (g * KPG + c2)], accA[i][j]);
        }
    }
}

// ---------------- launch ----------------------------------------------------
extern "C" void kernel_launch(void* const* d_in, const int* in_sizes, int n_in,
                              void* d_out, int out_size) {
    const float* h   = (const float*)d_in[0];
    const int*   src = (const int*)d_in[1];
    const int*   dst = (const int*)d_in[2];
    const float* W1f = (const float*)d_in[3];
    const float* b1f = (const float*)d_in[4];
    const float* W2f = (const float*)d_in[5];
    const float* b2f = (const float*)d_in[6];
    const float* W1p = (const float*)d_in[7];
    const float* b1p = (const float*)d_in[8];
    const float* W2p = (const float*)d_in[9];
    const float* b2p = (const float*)d_in[10];
    float* out = (float*)d_out;

    int* degi;
    cudaGetSymbolAddress((void**)&degi, g_degi);

    cudaFuncSetAttribute(fused_pool_kernel, cudaFuncAttributeMaxDynamicSharedMemorySize, FUSED_SMEM);
    cudaFuncSetAttribute(feat_fused_kernel, cudaFuncAttributeMaxDynamicSharedMemorySize, FEAT_SMEM);

    // prep
    zero_i<<<128, 256>>>(degi, (size_t)NN);
    fill_bucket_kernel<<<(EE + 255) / 256, 256>>>(src, dst);
    gather_x_kernel<<<(NN * 32 + 255) / 256, 256>>>(h);
    cvt_tiled_kernel<<<1366, 256>>>(W1f, W2f, W1p, W2p);

    // fused pool1+pool2+softmax -> assign
    fused_pool_kernel<<<dim3(16, NB), 256, FUSED_SMEM>>>(b1p, b2p);

    // feat branch (both layers fused)
    zero_f<<<1024, 256>>>(out, (size_t)out_size);
    feat_fused_kernel<<<250, 256, FEAT_SMEM>>>(b1f, b2f);

    // tmp gather, merged output GEMMs
    gather_tmp_kernel<<<(NN * 32 + 255) / 256, 256>>>();
    hpool_adj_kernel<<<dim3(NSPLIT, NB), 256>>>(out);
}